// round 15
// baseline (speedup 1.0000x reference)
#include <cuda_runtime.h>
#include <math.h>

#define N_PROP 1024
#define C_ALL 81
#define CF 80
#define DET 100
#define SCORE_THRESH 0.05f
#define NMS_THRESH 0.5f
#define IMG_W 1333.0f
#define IMG_H 800.0f
#define CAP 1024
#define FCAP 256
#define KEEP_CAP 16384
#define SURV_CAP 2048
#define NT 512
#define FULL 0xFFFFFFFFu

typedef unsigned long long ull;

// Scratch (allocation-free __device__ globals; zero at load, reset each run).
__device__ ull    g_ckey[CF][CAP];
__device__ float4 g_cbox[CF][CAP];
__device__ int    g_ccnt[CF];
__device__ ull    g_keep_key[KEEP_CAP];
__device__ float4 g_keep_box[KEEP_CAP];
__device__ int    g_hist[2048];
__device__ int    g_keep_count = 0;
__device__ int    g_arrive = 0;
__device__ int    g_done = 0;

__device__ __forceinline__ void write_keep(int slot, int cf, int pos,
                                           ull srckey, float4 box) {
    if (slot < 0 || slot >= KEEP_CAP) return;
    unsigned flat = (unsigned)(cf * N_PROP + pos);          // < 2^17
    unsigned sb = (unsigned)(srckey >> 32);
    // kept key: [63:32]=score, [31:15]=(0x1FFFF-flat), [14:0]=slot
    ull kk = ((ull)sb << 32) | ((ull)(0x1FFFFu - flat) << 15)
           | (ull)(slot & 0x7FFF);
    g_keep_key[slot] = kk;
    g_keep_box[slot] = box;
    atomicAdd(&g_hist[(unsigned)(kk >> 52) & 0x7FFu], 1);
}

// ---------------------------------------------------------------------------
// Fused kernel: 80 blocks x 512.
//   Phase 1: warp per proposal (1280 warps >= 1024 props), conditional loads.
//   Spin barrier across the 80 co-resident blocks (single wave).
//   Phase 2: warp 0 per-class NMS; last block runs the top-100 (512 thr).
// ---------------------------------------------------------------------------
__global__ void __launch_bounds__(NT) fused_all(const float* __restrict__ logits,
                                                const float* __restrict__ rel,
                                                const float* __restrict__ props,
                                                float* __restrict__ out) {
    int cf = blockIdx.x;
    int tid = threadIdx.x;
    int lane = tid & 31;
    int warp = tid >> 5;

    __shared__ ull    skey[64];     // raw keys by slot
    __shared__ ull    skey2[64];    // keys by sorted rank
    __shared__ float4 sbox2[64];    // boxes by sorted rank
    __shared__ ull    ssup[64];     // suppression mask per sorted row
    __shared__ ull    S[SURV_CAP];  // topk survivor keys (last block only)
    __shared__ int    shist[2048];  // histogram copy (last block only)
    __shared__ ull    fkey[FCAP];   // fallback
    __shared__ float4 fbox[FCAP];
    __shared__ unsigned char fsupp[FCAP];
    __shared__ int    chunk[NT];
    __shared__ int    s_last, s_cnt, s_bstar, s_m;

    // ================= Phase 1: prep (warp per proposal) =================
    const float CLIP = 4.135166556742356f;  // log(1000/16)
    int n = cf * 16 + warp;                 // 0..1279
    if (n < N_PROP) {
        const float* L = logits + n * C_ALL;
        float a = L[lane];
        float b = L[lane + 32];
        float c = (lane + 64 < C_ALL) ? L[lane + 64] : -1e30f;
        float mx = fmaxf(a, fmaxf(b, c));
        #pragma unroll
        for (int off = 16; off > 0; off >>= 1)
            mx = fmaxf(mx, __shfl_xor_sync(FULL, mx, off));
        float ea = __expf(a - mx), eb = __expf(b - mx);
        float ec = (lane + 64 < C_ALL) ? __expf(c - mx) : 0.f;
        float s = ea + eb + ec;
        #pragma unroll
        for (int off = 16; off > 0; off >>= 1)
            s += __shfl_xor_sync(FULL, s, off);
        float rinv = __fdividef(1.0f, s);

        float4 p = ((const float4*)props)[n];
        float w = p.z - p.x + 1.0f, h = p.w - p.y + 1.0f;
        float cx = p.x + 0.5f * w, cy = p.y + 0.5f * h;

        #pragma unroll
        for (int q = 0; q < 3; ++q) {
            int cls = lane + 32 * q;
            if (cls < 1 || cls >= C_ALL) continue;
            float e = (q == 0) ? ea : (q == 1) ? eb : ec;
            float prob = e * rinv;
            if (prob > SCORE_THRESH) {
                int cc = cls - 1;
                // atomic + rel load issued FIRST so their latency overlaps decode
                int slot = atomicAdd(&g_ccnt[cc], 1);
                float4 r4 = *(const float4*)(rel + n * (4 * C_ALL) + 4 * cls);
                float dx = r4.x * 0.1f;
                float dy = r4.y * 0.1f;
                float dw = fminf(r4.z * 0.2f, CLIP);
                float dh = fminf(r4.w * 0.2f, CLIP);
                float pcx = dx * w + cx, pcy = dy * h + cy;
                float pw = __expf(dw) * w, ph = __expf(dh) * h;
                float x1 = pcx - 0.5f * pw;
                float y1 = pcy - 0.5f * ph;
                float x2 = pcx + 0.5f * pw - 1.0f;
                float y2 = pcy + 0.5f * ph - 1.0f;
                x1 = fminf(fmaxf(x1, 0.f), IMG_W - 1.f);
                x2 = fminf(fmaxf(x2, 0.f), IMG_W - 1.f);
                y1 = fminf(fmaxf(y1, 0.f), IMG_H - 1.f);
                y2 = fminf(fmaxf(y2, 0.f), IMG_H - 1.f);
                if (slot >= 0 && slot < CAP) {
                    g_cbox[cc][slot] = make_float4(x1, y1, x2, y2);
                    // key: [63:32]=score, [19:10]=(1023-n) idx-asc ties, [9:0]=slot
                    g_ckey[cc][slot] = ((ull)__float_as_uint(prob) << 32)
                                     | ((ull)(unsigned)(1023 - n) << 10)
                                     | (ull)(unsigned)slot;
                }
            }
        }
    }

    // ===== inter-block spin barrier (80 blocks, single wave, co-resident) ====
    __threadfence();        // release: scatter visible before arrive
    __syncthreads();        // whole block done with prep
    if (tid == 0) {
        atomicAdd(&g_arrive, 1);
        while (*(volatile int*)&g_arrive < CF) { __nanosleep(64); }
        __threadfence();    // acquire
    }
    __syncthreads();

    // ================= Phase 2: per-class NMS (warp 0) =================
    if (warp == 0) {
        // speculative loads (memory always valid) issued alongside ccnt load
        int c = __ldcg(&g_ccnt[cf]);
        ull keyA = __ldcg(&g_ckey[cf][lane]);
        ull keyB = __ldcg(&g_ckey[cf][lane + 32]);
        float4 bA = __ldcg(&g_cbox[cf][lane]);
        float4 bB = __ldcg(&g_cbox[cf][lane + 32]);
        if (c > CAP) c = CAP;

        if (c > 0 && c <= 64) {
            if (lane >= c)      { keyA = 0ull; bA = make_float4(0, 0, 0, 0); }
            if (lane + 32 >= c) { keyB = 0ull; bB = make_float4(0, 0, 0, 0); }

            skey[lane] = keyA;
            skey[lane + 32] = keyB;
            __syncwarp();

            // rank by counting (keys unique): rank = #{keys > mine}
            int rankA = 0, rankB = 0;
            for (int j = 0; j < c; ++j) {
                ull kj = skey[j];
                rankA += (kj > keyA);
                rankB += (kj > keyB);
            }
            if (lane < c)      { skey2[rankA] = keyA; sbox2[rankA] = bA; }
            if (lane + 32 < c) { skey2[rankB] = keyB; sbox2[rankB] = bB; }
            __syncwarp();

            // suppression matrix: row i suppresses j>i if IoU > thresh
            #pragma unroll
            for (int half = 0; half < 2; ++half) {
                int i = lane + 32 * half;
                if (i < c) {
                    float4 bi = sbox2[i];
                    float ai = (bi.z - bi.x + 1.f) * (bi.w - bi.y + 1.f);
                    ull msk = 0ull;
                    for (int j = i + 1; j < c; ++j) {
                        float4 bj = sbox2[j];
                        float aj = (bj.z - bj.x + 1.f) * (bj.w - bj.y + 1.f);
                        float iw = fminf(bi.z, bj.z) - fmaxf(bi.x, bj.x) + 1.f;
                        float ih = fminf(bi.w, bj.w) - fmaxf(bi.y, bj.y) + 1.f;
                        float inter = fmaxf(iw, 0.f) * fmaxf(ih, 0.f);
                        if (inter > NMS_THRESH * (ai + aj - inter))
                            msk |= (1ull << j);
                    }
                    ssup[i] = msk;
                }
            }
            __syncwarp();

            // greedy over masks (all lanes redundantly; broadcast LDS reads)
            ull rem = (c >= 64) ? ~0ull : ((1ull << c) - 1ull);
            ull keep = 0ull;
            while (rem) {
                int r = __ffsll(rem) - 1;
                ull bit = 1ull << r;
                keep |= bit;
                rem &= ~bit;
                rem &= ~ssup[r];
            }

            int kc = __popcll(keep);
            int base = 0;
            if (lane == 0 && kc > 0) base = atomicAdd(&g_keep_count, kc);
            base = __shfl_sync(FULL, base, 0);
            #pragma unroll
            for (int half = 0; half < 2; ++half) {
                int i = lane + 32 * half;
                if (i < c && ((keep >> i) & 1ull)) {
                    int rank = __popcll(keep & ((1ull << i) - 1ull));
                    write_keep(base + rank, cf, i, skey2[i], sbox2[i]);
                }
            }
        } else if (c > 64) {
            // ---- fallback (practically unreachable; clamped to FCAP) ----
            if (c > FCAP) c = FCAP;
            for (int i = lane; i < c; i += 32) fkey[i] = __ldcg(&g_ckey[cf][i]);
            __syncwarp();
            for (int i = lane; i < c; i += 32) {
                ull ki = fkey[i];
                int rk = 0;
                for (int j = 0; j < c; ++j) rk += (fkey[j] > ki);
                fbox[rk] = __ldcg(&g_cbox[cf][(int)(ki & 0x3FFu)]);
                fsupp[rk] = (unsigned char)0;
            }
            __syncwarp();
            ull myk2[8]; int myr2[8]; int nown = 0;
            for (int i = lane; i < c; i += 32) {
                ull ki = fkey[i];
                int rk = 0;
                for (int j = 0; j < c; ++j) rk += (fkey[j] > ki);
                myk2[nown] = ki; myr2[nown] = rk; nown++;
            }
            __syncwarp();
            for (int q = 0; q < nown; ++q) fkey[myr2[q]] = myk2[q];
            __syncwarp();
            for (int r = 0; r < c; ++r) {
                if (!fsupp[r]) {
                    float4 pb = fbox[r];
                    float pa = (pb.z - pb.x + 1.f) * (pb.w - pb.y + 1.f);
                    for (int j = r + 1 + lane; j < c; j += 32) {
                        if (!fsupp[j]) {
                            float4 q = fbox[j];
                            float qa = (q.z - q.x + 1.f) * (q.w - q.y + 1.f);
                            float iw = fminf(pb.z, q.z) - fmaxf(pb.x, q.x) + 1.f;
                            float ih = fminf(pb.w, q.w) - fmaxf(pb.y, q.y) + 1.f;
                            float inter = fmaxf(iw, 0.f) * fmaxf(ih, 0.f);
                            if (inter > NMS_THRESH * (pa + qa - inter)) fsupp[j] = 1;
                        }
                    }
                }
                __syncwarp();
            }
            int total = 0;
            for (int b = 0; b < c; b += 32) {
                bool kept = (b + lane < c) && !fsupp[b + lane];
                total += __popc(__ballot_sync(FULL, kept));
            }
            int base = 0;
            if (lane == 0) base = atomicAdd(&g_keep_count, total);
            base = __shfl_sync(FULL, base, 0);
            int before = 0;
            for (int b = 0; b < c; b += 32) {
                bool kept = (b + lane < c) && !fsupp[b + lane];
                unsigned bal = __ballot_sync(FULL, kept);
                if (kept) {
                    int rank = before + __popc(bal & ((1u << lane) - 1u));
                    write_keep(base + rank, cf, b + lane, fkey[b + lane], fbox[b + lane]);
                }
                before += __popc(bal);
            }
        }

        // reset + publish
        if (lane == 0) g_ccnt[cf] = 0;
        __threadfence();
        __syncwarp();
        if (lane == 0) {
            int t = atomicAdd(&g_done, 1);
            s_last = (t == CF - 1);
        }
    }
    __syncthreads();
    if (!s_last) return;
    __threadfence();

    // ================= top-100 (512 threads, last block) =================
    if (tid == 0) { s_cnt = 0; s_bstar = 0; s_m = 0; }
    for (int i = tid; i < 6 * DET; i += NT) out[i] = 0.f;

    // speculative key preload (4/thread covers 2048), concurrent with hist copy
    ull kk[4];
    #pragma unroll
    for (int q = 0; q < 4; ++q) kk[q] = __ldcg(&g_keep_key[tid + NT * q]);

    // copy histogram to shared + per-thread chunk sums (4 buckets/thread)
    {
        int s = 0;
        #pragma unroll
        for (int j = 0; j < 4; ++j) {
            int v = __ldcg(&g_hist[tid * 4 + j]);
            shist[tid * 4 + j] = v;
            s += v;
        }
        chunk[tid] = s;
    }
    __syncthreads();

    // warp 0: total count m + bucket of the DET-th largest key (high -> low)
    if (warp == 0) {
        int g = 0;
        #pragma unroll
        for (int j = 0; j < 16; ++j) g += chunk[lane * 16 + j];
        int suf = g;      // inclusive suffix over lanes >= lane
        #pragma unroll
        for (int off = 1; off < 32; off <<= 1) {
            int v = __shfl_down_sync(FULL, suf, off);
            if (lane + off < 32) suf += v;
        }
        if (lane == 0) s_m = suf;   // hist total == number of written keeps
        int sufExcl = suf - g;
        if (sufExcl < DET && suf >= DET) {
            int cum = sufExcl;
            for (int t16 = lane * 16 + 15; t16 >= lane * 16; --t16) {
                int nc = cum + chunk[t16];
                if (nc >= DET) {
                    for (int b = t16 * 4 + 3; b >= t16 * 4; --b) {
                        cum += shist[b];
                        if (cum >= DET) { s_bstar = b; break; }
                    }
                    break;
                }
                cum = nc;
            }
        }
    }
    __syncthreads();
    unsigned bstar = (unsigned)s_bstar;
    int m = s_m;
    if (m > KEEP_CAP) m = KEEP_CAP;

    // compact survivors (bucket >= b*) from preloaded registers.
    // Warp-ballot compaction: one shared atomic per warp-round instead of
    // one per survivor (pool order is irrelevant — ranking is exact).
    #pragma unroll
    for (int q = 0; q < 4; ++q) {
        int i = tid + NT * q;
        bool surv = (i < m) && (((unsigned)(kk[q] >> 52) & 0x7FFu) >= bstar);
        unsigned bal = __ballot_sync(FULL, surv);
        int cnt = __popc(bal);
        int wbase = 0;
        if (lane == 0 && cnt > 0) wbase = atomicAdd(&s_cnt, cnt);
        wbase = __shfl_sync(FULL, wbase, 0);
        if (surv) {
            int p = wbase + __popc(bal & ((1u << lane) - 1u));
            if (p >= 0 && p < SURV_CAP) S[p] = kk[q];
        }
    }
    for (int i0 = 4 * NT; i0 < m; i0 += NT) {
        int i = i0 + tid;
        ull k = (i < m) ? __ldcg(&g_keep_key[i]) : 0ull;
        bool surv = (i < m) && (((unsigned)(k >> 52) & 0x7FFu) >= bstar);
        unsigned bal = __ballot_sync(FULL, surv);
        int cnt = __popc(bal);
        int wbase = 0;
        if (lane == 0 && cnt > 0) wbase = atomicAdd(&s_cnt, cnt);
        wbase = __shfl_sync(FULL, wbase, 0);
        if (surv) {
            int p = wbase + __popc(bal & ((1u << lane) - 1u));
            if (p >= 0 && p < SURV_CAP) S[p] = k;
        }
    }
    __syncthreads();
    int sc = s_cnt;
    if (sc > SURV_CAP) sc = SURV_CAP;

    // exact rank of each survivor (keys unique) == global rank.
    // Box load hoisted ABOVE the rank loop so its latency overlaps the scan.
    for (int i = tid; i < sc; i += NT) {
        ull k = S[i];
        int slot = (int)(k & 0x7FFFu);
        if (slot >= KEEP_CAP) slot = 0;
        float4 b = __ldcg(&g_keep_box[slot]);
        int rank = 0;
        for (int j = 0; j < sc; ++j) rank += (S[j] > k);
        if (rank < DET) {
            float score = __uint_as_float((unsigned)(k >> 32));
            unsigned flat = 0x1FFFFu - (unsigned)((k >> 15) & 0x1FFFFu);
            out[rank * 4 + 0] = b.x;
            out[rank * 4 + 1] = b.y;
            out[rank * 4 + 2] = b.z;
            out[rank * 4 + 3] = b.w;
            out[4 * DET + rank] = score;
            out[5 * DET + rank] = (float)(flat / N_PROP + 1);
        }
    }

    // reset global state for next graph replay (all blocks already past spin:
    // g_done==CF implies every block observed g_arrive==CF)
    __syncthreads();
    #pragma unroll
    for (int j = 0; j < 4; ++j) g_hist[tid * 4 + j] = 0;
    if (tid == 0) { g_keep_count = 0; g_done = 0; g_arrive = 0; }
}

extern "C" void kernel_launch(void* const* d_in, const int* in_sizes, int n_in,
                              void* d_out, int out_size) {
    const float* class_logits = (const float*)d_in[0];   // [1024, 81]
    const float* box_regression = (const float*)d_in[1]; // [1024, 324]
    const float* proposals = (const float*)d_in[2];      // [1024, 4]
    float* out = (float*)d_out;                          // 600 floats

    fused_all<<<CF, NT>>>(class_logits, box_regression, proposals, out);
}

// round 16
// speedup vs baseline: 1.0243x; 1.0243x over previous
#include <cuda_runtime.h>
#include <math.h>

#define N_PROP 1024
#define C_ALL 81
#define CF 80
#define DET 100
#define SCORE_THRESH 0.05f
#define NMS_THRESH 0.5f
#define IMG_W 1333.0f
#define IMG_H 800.0f
#define CAP 1024
#define FCAP 256
#define KEEP_CAP 16384
#define SURV_CAP 2048
#define NT 512
#define FULL 0xFFFFFFFFu

typedef unsigned long long ull;

// Scratch (allocation-free __device__ globals; zero at load, reset each run).
__device__ ull    g_ckey[CF][CAP];
__device__ float4 g_cbox[CF][CAP];
__device__ int    g_ccnt[CF];
__device__ ull    g_keep_key[KEEP_CAP];
__device__ float4 g_keep_box[KEEP_CAP];
__device__ int    g_hist[2048];
__device__ int    g_keep_count = 0;
__device__ int    g_arrive = 0;
__device__ int    g_done = 0;

__device__ __forceinline__ unsigned fmono(float x) {
    unsigned u = __float_as_uint(x);
    return u ^ (((unsigned)((int)u >> 31)) | 0x80000000u);
}
__device__ __forceinline__ float funmono(unsigned m) {
    unsigned u = (m & 0x80000000u) ? (m ^ 0x80000000u) : ~m;
    return __uint_as_float(u);
}

__device__ __forceinline__ void write_keep(int slot, int cf, int pos,
                                           ull srckey, float4 box) {
    if (slot < 0 || slot >= KEEP_CAP) return;
    unsigned flat = (unsigned)(cf * N_PROP + pos);          // < 2^17
    unsigned sb = (unsigned)(srckey >> 32);
    // kept key: [63:32]=score, [31:15]=(0x1FFFF-flat), [14:0]=slot
    ull kk = ((ull)sb << 32) | ((ull)(0x1FFFFu - flat) << 15)
           | (ull)(slot & 0x7FFF);
    g_keep_key[slot] = kk;
    g_keep_box[slot] = box;
    atomicAdd(&g_hist[(unsigned)(kk >> 52) & 0x7FFu], 1);
}

// ---------------------------------------------------------------------------
// Fused kernel: 80 blocks x 512.
//   Phase 1: warp per proposal (1280 warps >= 1024 props), conditional loads.
//   Spin barrier across the 80 co-resident blocks (single wave).
//   Phase 2: warp 0 per-class NMS; last block runs the top-100 (512 thr).
// ---------------------------------------------------------------------------
__global__ void __launch_bounds__(NT) fused_all(const float* __restrict__ logits,
                                                const float* __restrict__ rel,
                                                const float* __restrict__ props,
                                                float* __restrict__ out) {
    int cf = blockIdx.x;
    int tid = threadIdx.x;
    int lane = tid & 31;
    int warp = tid >> 5;

    __shared__ ull    skey[64];     // raw keys by slot
    __shared__ ull    skey2[64];    // keys by sorted rank
    __shared__ float4 sbox2[64];    // boxes by sorted rank
    __shared__ ull    ssup[64];     // suppression mask per sorted row
    __shared__ ull    S[SURV_CAP];  // topk survivor keys (last block only)
    __shared__ int    shist[2048];  // histogram copy (last block only)
    __shared__ ull    fkey[FCAP];   // fallback
    __shared__ float4 fbox[FCAP];
    __shared__ unsigned char fsupp[FCAP];
    __shared__ int    chunk[NT];
    __shared__ int    s_last, s_cnt, s_bstar, s_m;

    // ================= Phase 1: prep (warp per proposal) =================
    const float CLIP = 4.135166556742356f;  // log(1000/16)
    int n = cf * 16 + warp;                 // 0..1279
    if (n < N_PROP) {
        const float* L = logits + n * C_ALL;
        float a = L[lane];
        float b = L[lane + 32];
        float c = (lane + 64 < C_ALL) ? L[lane + 64] : -1e30f;
        // exact warp max via one REDUX on monotone uint map
        float mx3 = fmaxf(a, fmaxf(b, c));
        float mx = funmono(__reduce_max_sync(FULL, fmono(mx3)));
        float ea = __expf(a - mx), eb = __expf(b - mx);
        float ec = (lane + 64 < C_ALL) ? __expf(c - mx) : 0.f;
        float s = ea + eb + ec;
        #pragma unroll
        for (int off = 16; off > 0; off >>= 1)
            s += __shfl_xor_sync(FULL, s, off);
        float rinv = __fdividef(1.0f, s);

        float4 p = ((const float4*)props)[n];
        float w = p.z - p.x + 1.0f, h = p.w - p.y + 1.0f;
        float cx = p.x + 0.5f * w, cy = p.y + 0.5f * h;

        #pragma unroll
        for (int q = 0; q < 3; ++q) {
            int cls = lane + 32 * q;
            if (cls < 1 || cls >= C_ALL) continue;
            float e = (q == 0) ? ea : (q == 1) ? eb : ec;
            float prob = e * rinv;
            if (prob > SCORE_THRESH) {
                int cc = cls - 1;
                // atomic + rel load issued FIRST so their latency overlaps decode
                int slot = atomicAdd(&g_ccnt[cc], 1);
                float4 r4 = *(const float4*)(rel + n * (4 * C_ALL) + 4 * cls);
                float dx = r4.x * 0.1f;
                float dy = r4.y * 0.1f;
                float dw = fminf(r4.z * 0.2f, CLIP);
                float dh = fminf(r4.w * 0.2f, CLIP);
                float pcx = dx * w + cx, pcy = dy * h + cy;
                float pw = __expf(dw) * w, ph = __expf(dh) * h;
                float x1 = pcx - 0.5f * pw;
                float y1 = pcy - 0.5f * ph;
                float x2 = pcx + 0.5f * pw - 1.0f;
                float y2 = pcy + 0.5f * ph - 1.0f;
                x1 = fminf(fmaxf(x1, 0.f), IMG_W - 1.f);
                x2 = fminf(fmaxf(x2, 0.f), IMG_W - 1.f);
                y1 = fminf(fmaxf(y1, 0.f), IMG_H - 1.f);
                y2 = fminf(fmaxf(y2, 0.f), IMG_H - 1.f);
                if (slot >= 0 && slot < CAP) {
                    g_cbox[cc][slot] = make_float4(x1, y1, x2, y2);
                    // key: [63:32]=score, [19:10]=(1023-n) idx-asc ties, [9:0]=slot
                    g_ckey[cc][slot] = ((ull)__float_as_uint(prob) << 32)
                                     | ((ull)(unsigned)(1023 - n) << 10)
                                     | (ull)(unsigned)slot;
                }
            }
        }
    }

    // ===== inter-block spin barrier (80 blocks, single wave, co-resident) ====
    __threadfence();        // release: scatter visible before arrive
    __syncthreads();        // whole block done with prep
    if (tid == 0) {
        atomicAdd(&g_arrive, 1);
        while (*(volatile int*)&g_arrive < CF) { __nanosleep(64); }
        __threadfence();    // acquire
    }
    __syncthreads();

    // ================= Phase 2: per-class NMS (warp 0) =================
    if (warp == 0) {
        // speculative loads (memory always valid) issued alongside ccnt load
        int c = __ldcg(&g_ccnt[cf]);
        ull keyA = __ldcg(&g_ckey[cf][lane]);
        ull keyB = __ldcg(&g_ckey[cf][lane + 32]);
        float4 bA = __ldcg(&g_cbox[cf][lane]);
        float4 bB = __ldcg(&g_cbox[cf][lane + 32]);
        if (c > CAP) c = CAP;

        if (c > 0 && c <= 64) {
            if (lane >= c)      { keyA = 0ull; bA = make_float4(0, 0, 0, 0); }
            if (lane + 32 >= c) { keyB = 0ull; bB = make_float4(0, 0, 0, 0); }

            skey[lane] = keyA;
            skey[lane + 32] = keyB;
            __syncwarp();

            // rank by counting (keys unique): rank = #{keys > mine}
            int rankA = 0, rankB = 0;
            for (int j = 0; j < c; ++j) {
                ull kj = skey[j];
                rankA += (kj > keyA);
                rankB += (kj > keyB);
            }
            if (lane < c)      { skey2[rankA] = keyA; sbox2[rankA] = bA; }
            if (lane + 32 < c) { skey2[rankB] = keyB; sbox2[rankB] = bB; }
            __syncwarp();

            // suppression matrix: row i suppresses j>i if IoU > thresh.
            // Balanced row pairing (lane, c-1-lane): per-lane inner-iteration
            // total = (c-1-lane) + lane = c-1, constant across lanes.
            #pragma unroll
            for (int half = 0; half < 2; ++half) {
                int i = (half == 0) ? lane : (c - 1 - lane);
                bool do_row = (half == 0) ? (i < c) : (i >= 32 && i < c);
                if (do_row) {
                    float4 bi = sbox2[i];
                    float ai = (bi.z - bi.x + 1.f) * (bi.w - bi.y + 1.f);
                    ull msk = 0ull;
                    for (int j = i + 1; j < c; ++j) {
                        float4 bj = sbox2[j];
                        float aj = (bj.z - bj.x + 1.f) * (bj.w - bj.y + 1.f);
                        float iw = fminf(bi.z, bj.z) - fmaxf(bi.x, bj.x) + 1.f;
                        float ih = fminf(bi.w, bj.w) - fmaxf(bi.y, bj.y) + 1.f;
                        float inter = fmaxf(iw, 0.f) * fmaxf(ih, 0.f);
                        if (inter > NMS_THRESH * (ai + aj - inter))
                            msk |= (1ull << j);
                    }
                    ssup[i] = msk;
                }
            }
            __syncwarp();

            // greedy over masks (all lanes redundantly; broadcast LDS reads)
            ull rem = (c >= 64) ? ~0ull : ((1ull << c) - 1ull);
            ull keep = 0ull;
            while (rem) {
                int r = __ffsll(rem) - 1;
                ull bit = 1ull << r;
                keep |= bit;
                rem &= ~bit;
                rem &= ~ssup[r];
            }

            int kc = __popcll(keep);
            int base = 0;
            if (lane == 0 && kc > 0) base = atomicAdd(&g_keep_count, kc);
            base = __shfl_sync(FULL, base, 0);
            #pragma unroll
            for (int half = 0; half < 2; ++half) {
                int i = lane + 32 * half;
                if (i < c && ((keep >> i) & 1ull)) {
                    int rank = __popcll(keep & ((1ull << i) - 1ull));
                    write_keep(base + rank, cf, i, skey2[i], sbox2[i]);
                }
            }
        } else if (c > 64) {
            // ---- fallback (practically unreachable; clamped to FCAP) ----
            if (c > FCAP) c = FCAP;
            for (int i = lane; i < c; i += 32) fkey[i] = __ldcg(&g_ckey[cf][i]);
            __syncwarp();
            for (int i = lane; i < c; i += 32) {
                ull ki = fkey[i];
                int rk = 0;
                for (int j = 0; j < c; ++j) rk += (fkey[j] > ki);
                fbox[rk] = __ldcg(&g_cbox[cf][(int)(ki & 0x3FFu)]);
                fsupp[rk] = (unsigned char)0;
            }
            __syncwarp();
            ull myk2[8]; int myr2[8]; int nown = 0;
            for (int i = lane; i < c; i += 32) {
                ull ki = fkey[i];
                int rk = 0;
                for (int j = 0; j < c; ++j) rk += (fkey[j] > ki);
                myk2[nown] = ki; myr2[nown] = rk; nown++;
            }
            __syncwarp();
            for (int q = 0; q < nown; ++q) fkey[myr2[q]] = myk2[q];
            __syncwarp();
            for (int r = 0; r < c; ++r) {
                if (!fsupp[r]) {
                    float4 pb = fbox[r];
                    float pa = (pb.z - pb.x + 1.f) * (pb.w - pb.y + 1.f);
                    for (int j = r + 1 + lane; j < c; j += 32) {
                        if (!fsupp[j]) {
                            float4 q = fbox[j];
                            float qa = (q.z - q.x + 1.f) * (q.w - q.y + 1.f);
                            float iw = fminf(pb.z, q.z) - fmaxf(pb.x, q.x) + 1.f;
                            float ih = fminf(pb.w, q.w) - fmaxf(pb.y, q.y) + 1.f;
                            float inter = fmaxf(iw, 0.f) * fmaxf(ih, 0.f);
                            if (inter > NMS_THRESH * (pa + qa - inter)) fsupp[j] = 1;
                        }
                    }
                }
                __syncwarp();
            }
            int total = 0;
            for (int b = 0; b < c; b += 32) {
                bool kept = (b + lane < c) && !fsupp[b + lane];
                total += __popc(__ballot_sync(FULL, kept));
            }
            int base = 0;
            if (lane == 0) base = atomicAdd(&g_keep_count, total);
            base = __shfl_sync(FULL, base, 0);
            int before = 0;
            for (int b = 0; b < c; b += 32) {
                bool kept = (b + lane < c) && !fsupp[b + lane];
                unsigned bal = __ballot_sync(FULL, kept);
                if (kept) {
                    int rank = before + __popc(bal & ((1u << lane) - 1u));
                    write_keep(base + rank, cf, b + lane, fkey[b + lane], fbox[b + lane]);
                }
                before += __popc(bal);
            }
        }

        // reset + publish
        if (lane == 0) g_ccnt[cf] = 0;
        __threadfence();
        __syncwarp();
        if (lane == 0) {
            int t = atomicAdd(&g_done, 1);
            s_last = (t == CF - 1);
        }
    }
    __syncthreads();
    if (!s_last) return;
    __threadfence();

    // ================= top-100 (512 threads, last block) =================
    if (tid == 0) { s_cnt = 0; s_bstar = 0; s_m = 0; }
    for (int i = tid; i < 6 * DET; i += NT) out[i] = 0.f;

    // speculative key preload (4/thread covers 2048), concurrent with hist copy
    ull kk[4];
    #pragma unroll
    for (int q = 0; q < 4; ++q) kk[q] = __ldcg(&g_keep_key[tid + NT * q]);

    // copy histogram to shared + per-thread chunk sums (4 buckets/thread)
    {
        int s = 0;
        #pragma unroll
        for (int j = 0; j < 4; ++j) {
            int v = __ldcg(&g_hist[tid * 4 + j]);
            shist[tid * 4 + j] = v;
            s += v;
        }
        chunk[tid] = s;
    }
    __syncthreads();

    // warp 0: total count m + bucket of the DET-th largest key (high -> low)
    if (warp == 0) {
        int g = 0;
        #pragma unroll
        for (int j = 0; j < 16; ++j) g += chunk[lane * 16 + j];
        int suf = g;      // inclusive suffix over lanes >= lane
        #pragma unroll
        for (int off = 1; off < 32; off <<= 1) {
            int v = __shfl_down_sync(FULL, suf, off);
            if (lane + off < 32) suf += v;
        }
        if (lane == 0) s_m = suf;   // hist total == number of written keeps
        int sufExcl = suf - g;
        if (sufExcl < DET && suf >= DET) {
            int cum = sufExcl;
            for (int t16 = lane * 16 + 15; t16 >= lane * 16; --t16) {
                int nc = cum + chunk[t16];
                if (nc >= DET) {
                    for (int b = t16 * 4 + 3; b >= t16 * 4; --b) {
                        cum += shist[b];
                        if (cum >= DET) { s_bstar = b; break; }
                    }
                    break;
                }
                cum = nc;
            }
        }
    }
    __syncthreads();
    unsigned bstar = (unsigned)s_bstar;
    int m = s_m;
    if (m > KEEP_CAP) m = KEEP_CAP;

    // compact survivors (bucket >= b*) from preloaded registers.
    #pragma unroll
    for (int q = 0; q < 4; ++q) {
        int i = tid + NT * q;
        bool surv = (i < m) && (((unsigned)(kk[q] >> 52) & 0x7FFu) >= bstar);
        unsigned bal = __ballot_sync(FULL, surv);
        int cnt = __popc(bal);
        int wbase = 0;
        if (lane == 0 && cnt > 0) wbase = atomicAdd(&s_cnt, cnt);
        wbase = __shfl_sync(FULL, wbase, 0);
        if (surv) {
            int p = wbase + __popc(bal & ((1u << lane) - 1u));
            if (p >= 0 && p < SURV_CAP) S[p] = kk[q];
        }
    }
    for (int i0 = 4 * NT; i0 < m; i0 += NT) {
        int i = i0 + tid;
        ull k = (i < m) ? __ldcg(&g_keep_key[i]) : 0ull;
        bool surv = (i < m) && (((unsigned)(k >> 52) & 0x7FFu) >= bstar);
        unsigned bal = __ballot_sync(FULL, surv);
        int cnt = __popc(bal);
        int wbase = 0;
        if (lane == 0 && cnt > 0) wbase = atomicAdd(&s_cnt, cnt);
        wbase = __shfl_sync(FULL, wbase, 0);
        if (surv) {
            int p = wbase + __popc(bal & ((1u << lane) - 1u));
            if (p >= 0 && p < SURV_CAP) S[p] = k;
        }
    }
    __syncthreads();
    int sc = s_cnt;
    if (sc > SURV_CAP) sc = SURV_CAP;

    // exact rank of each survivor (keys unique) == global rank.
    // Box load hoisted ABOVE the rank loop so its latency overlaps the scan.
    for (int i = tid; i < sc; i += NT) {
        ull k = S[i];
        int slot = (int)(k & 0x7FFFu);
        if (slot >= KEEP_CAP) slot = 0;
        float4 b = __ldcg(&g_keep_box[slot]);
        int rank = 0;
        for (int j = 0; j < sc; ++j) rank += (S[j] > k);
        if (rank < DET) {
            float score = __uint_as_float((unsigned)(k >> 32));
            unsigned flat = 0x1FFFFu - (unsigned)((k >> 15) & 0x1FFFFu);
            out[rank * 4 + 0] = b.x;
            out[rank * 4 + 1] = b.y;
            out[rank * 4 + 2] = b.z;
            out[rank * 4 + 3] = b.w;
            out[4 * DET + rank] = score;
            out[5 * DET + rank] = (float)(flat / N_PROP + 1);
        }
    }

    // reset global state for next graph replay (all blocks already past spin:
    // g_done==CF implies every block observed g_arrive==CF)
    __syncthreads();
    #pragma unroll
    for (int j = 0; j < 4; ++j) g_hist[tid * 4 + j] = 0;
    if (tid == 0) { g_keep_count = 0; g_done = 0; g_arrive = 0; }
}

extern "C" void kernel_launch(void* const* d_in, const int* in_sizes, int n_in,
                              void* d_out, int out_size) {
    const float* class_logits = (const float*)d_in[0];   // [1024, 81]
    const float* box_regression = (const float*)d_in[1]; // [1024, 324]
    const float* proposals = (const float*)d_in[2];      // [1024, 4]
    float* out = (float*)d_out;                          // 600 floats

    fused_all<<<CF, NT>>>(class_logits, box_regression, proposals, out);
}